// round 4
// baseline (speedup 1.0000x reference)
#include <cuda_runtime.h>
#include <cuda_bf16.h>
#include <cstdint>

typedef unsigned long long ull;

#define B_  32
#define S_  128
#define H_  512
#define D_  512
#define V_  32000
#define F_  768
#define G4  2048   // 4*H
#define NCTA 128   // persistent recurrence grid size

// ---------------- scratch (device globals; no allocation allowed) ----------------
__device__ float g_yim[B_ * D_];
__device__ float g_Xg[(S_ + 1) * B_ * D_];
__device__ float g_xU[(S_ + 1) * B_ * G4];
__device__ float g_Wcat[1024 * G4];
__device__ float g_b1eff[G4];
__device__ float g_hcat[B_ * 1024];              // [h1 | h0] per row
__device__ float g_c0s[B_ * H_];
__device__ float g_c1s[B_ * H_];
__device__ float g_part[16 * B_ * G4];
__device__ float g_H1s[S_ * B_ * H_];
__device__ float g_ys[S_ * B_ * D_];
__device__ unsigned g_bar[2];                    // grid barrier: arrive, release

// ---------------- packed fp32x2 helpers ----------------
__device__ __forceinline__ ull pack2(float x, float y) {
    ull r; asm("mov.b64 %0, {%1, %2};" : "=l"(r) : "f"(x), "f"(y)); return r;
}
__device__ __forceinline__ void ffma2(ull& d, ull a, ull b) {
    asm("fma.rn.f32x2 %0, %1, %2, %0;" : "+l"(d) : "l"(a), "l"(b));
}
__device__ __forceinline__ float2 unpack2(ull v) {
    float2 r; asm("mov.b64 {%0, %1}, %2;" : "=f"(r.x), "=f"(r.y) : "l"(v)); return r;
}

__device__ __forceinline__ uint32_t smem_u32(const void* p) {
    return (uint32_t)__cvta_generic_to_shared(p);
}

// ---------------- init ----------------
__global__ void init_state_kernel(const float* __restrict__ h0,
                                  const float* __restrict__ c0,
                                  float* __restrict__ hcat,
                                  float* __restrict__ c0s,
                                  float* __restrict__ c1s) {
    int idx = blockIdx.x * 256 + threadIdx.x;   // 32768
    int l = idx >> 14, b = (idx >> 9) & 31, j = idx & 511;
    float h = h0[idx], c = c0[idx];
    if (l == 0) { hcat[b * 1024 + 512 + j] = h; c0s[b * 512 + j] = c; }
    else        { hcat[b * 1024 + j] = h;       c1s[b * 512 + j] = c; }
    if (idx == 0) { g_bar[0] = 0u; g_bar[1] = 0u; }
}

// ---------------- gather ----------------
__global__ void gather_kernel(const float* __restrict__ yim,
                              const float* __restrict__ embed,
                              const int* __restrict__ tokens,
                              float* __restrict__ Xg) {
    int v = blockIdx.x * 256 + threadIdx.x;
    int d4 = v & 127;
    int bt = v >> 7;
    int b = bt & 31;
    int t = bt >> 5;
    const float4* src;
    if (t == 0) src = (const float4*)(yim + b * 512);
    else        src = (const float4*)(embed + (size_t)tokens[b * 128 + (t - 1)] * 512);
    ((float4*)Xg)[v] = src[d4];
}

// ---------------- b1eff ----------------
__global__ void b1eff_kernel(const float* __restrict__ bw, const float* __restrict__ bu,
                             const float* __restrict__ bxh, const float* __restrict__ Uh,
                             float* __restrict__ b1) {
    int n = blockIdx.x * 256 + threadIdx.x;
    float acc = bw[2048 + n] + bu[2048 + n];
    const float* U1 = Uh + 512 * 2048;
    for (int k = 0; k < 512; k++) acc += bxh[k] * U1[k * 2048 + n];
    b1[n] = acc;
}

// ---------------- fp32 SGEMM (small matrices only) ----------------
__global__ __launch_bounds__(256, 2) void sgemm_kernel(const float* __restrict__ A,
                                                       const float* __restrict__ Bm,
                                                       const float* __restrict__ bias,
                                                       float* __restrict__ C,
                                                       int M, int N, int K, int permute) {
    __shared__ __align__(16) float As[16][132];
    __shared__ __align__(16) float Bs[16][128];
    int tid = threadIdx.x;
    int m0 = blockIdx.y * 128, n0 = blockIdx.x * 128;
    int a_m = tid >> 2, a_k = (tid & 3) << 2;
    int b_k = tid >> 5, b_n = (tid & 31) << 2;
    int tm0 = (tid >> 4) << 3, tn0 = (tid & 15) << 3;
    ull acc[8][4];
    #pragma unroll
    for (int i = 0; i < 8; i++)
        #pragma unroll
        for (int j = 0; j < 4; j++) acc[i][j] = 0ULL;

    for (int k0 = 0; k0 < K; k0 += 16) {
        #pragma unroll
        for (int h = 0; h < 2; h++) {
            int gm = m0 + a_m + h * 64;
            float4 av = make_float4(0.f, 0.f, 0.f, 0.f);
            if (gm < M) av = *(const float4*)(A + (size_t)gm * K + k0 + a_k);
            As[a_k + 0][a_m + h * 64] = av.x;
            As[a_k + 1][a_m + h * 64] = av.y;
            As[a_k + 2][a_m + h * 64] = av.z;
            As[a_k + 3][a_m + h * 64] = av.w;
        }
        #pragma unroll
        for (int h = 0; h < 2; h++) {
            int gk = k0 + b_k + h * 8;
            *(float4*)&Bs[b_k + h * 8][b_n] = *(const float4*)(Bm + (size_t)gk * N + n0 + b_n);
        }
        __syncthreads();
        #pragma unroll
        for (int kk = 0; kk < 16; kk++) {
            float4 a0 = *(const float4*)&As[kk][tm0];
            float4 a1 = *(const float4*)&As[kk][tm0 + 4];
            ull b2[4];
            #pragma unroll
            for (int j = 0; j < 4; j++) b2[j] = *(const ull*)&Bs[kk][tn0 + 2 * j];
            float av[8] = {a0.x, a0.y, a0.z, a0.w, a1.x, a1.y, a1.z, a1.w};
            #pragma unroll
            for (int i = 0; i < 8; i++) {
                ull a2 = pack2(av[i], av[i]);
                #pragma unroll
                for (int j = 0; j < 4; j++) ffma2(acc[i][j], a2, b2[j]);
            }
        }
        __syncthreads();
    }
    #pragma unroll
    for (int i = 0; i < 8; i++) {
        int r = m0 + tm0 + i;
        if (r < M) {
            int ro = permute ? ((r & 31) * 128 + (r >> 5)) : r;
            float o_[8];
            #pragma unroll
            for (int j = 0; j < 4; j++) {
                float2 v = unpack2(acc[i][j]);
                o_[2 * j] = v.x; o_[2 * j + 1] = v.y;
            }
            if (bias) {
                #pragma unroll
                for (int j = 0; j < 8; j++) o_[j] += bias[n0 + tn0 + j];
            }
            float* cp = C + (size_t)ro * N + n0 + tn0;
            *(float4*)cp = make_float4(o_[0], o_[1], o_[2], o_[3]);
            *(float4*)(cp + 4) = make_float4(o_[4], o_[5], o_[6], o_[7]);
        }
    }
}

// ---------------- bf16 split-3 tensor-core GEMM ----------------
// C = A[M,K]fp32 @ B[K,N]fp32 (+bias), via a=ahi+alo, b=bhi+blo bf16 splits,
// D += ahi*bhi + ahi*blo + alo*bhi. Requires N%128==0, K%16==0.
#define LDSM4(r, addr) asm volatile( \
    "ldmatrix.sync.aligned.m8n8.x4.shared.b16 {%0,%1,%2,%3}, [%4];" \
    : "=r"((r)[0]), "=r"((r)[1]), "=r"((r)[2]), "=r"((r)[3]) : "r"(addr))
#define LDSM4T(r, addr) asm volatile( \
    "ldmatrix.sync.aligned.m8n8.x4.trans.shared.b16 {%0,%1,%2,%3}, [%4];" \
    : "=r"((r)[0]), "=r"((r)[1]), "=r"((r)[2]), "=r"((r)[3]) : "r"(addr))
#define MMA16816(d, a, b) asm volatile( \
    "mma.sync.aligned.m16n8k16.row.col.f32.bf16.bf16.f32 " \
    "{%0,%1,%2,%3}, {%4,%5,%6,%7}, {%8,%9}, {%0,%1,%2,%3};" \
    : "+f"((d)[0]), "+f"((d)[1]), "+f"((d)[2]), "+f"((d)[3]) \
    : "r"((a)[0]), "r"((a)[1]), "r"((a)[2]), "r"((a)[3]), "r"((b)[0]), "r"((b)[1]))

__device__ __forceinline__ uint32_t bfpack(float x, float y) {
    __nv_bfloat16 a = __float2bfloat16_rn(x);
    __nv_bfloat16 b = __float2bfloat16_rn(y);
    return ((uint32_t)__bfloat16_as_ushort(b) << 16) | (uint32_t)__bfloat16_as_ushort(a);
}

__global__ __launch_bounds__(256) void bf3_gemm_kernel(const float* __restrict__ A,
                                                       const float* __restrict__ Bm,
                                                       const float* __restrict__ bias,
                                                       float* __restrict__ C,
                                                       int M, int N, int K, int permute) {
    __shared__ __align__(16) __nv_bfloat16 Ahs[128][24];
    __shared__ __align__(16) __nv_bfloat16 Als[128][24];
    __shared__ __align__(16) __nv_bfloat16 Bhs[16][136];
    __shared__ __align__(16) __nv_bfloat16 Bls[16][136];
    int tid = threadIdx.x;
    int lane = tid & 31, wid = tid >> 5;
    int wm = wid >> 2, wn = wid & 3;           // 2 x 4 warps, warp tile 64m x 32n
    int m0 = blockIdx.y * 128, n0 = blockIdx.x * 128;

    // ldmatrix source addresses (fixed per thread)
    uint32_t aAh[4], aAl[4], aBh[2], aBl[2];
    {
        int r = lane & 15, c = (lane >> 4) * 8;
        #pragma unroll
        for (int i = 0; i < 4; i++) {
            aAh[i] = smem_u32(&Ahs[wm * 64 + i * 16 + r][c]);
            aAl[i] = smem_u32(&Als[wm * 64 + i * 16 + r][c]);
        }
        #pragma unroll
        for (int j2 = 0; j2 < 2; j2++) {
            aBh[j2] = smem_u32(&Bhs[r][wn * 32 + j2 * 16 + c]);
            aBl[j2] = smem_u32(&Bls[r][wn * 32 + j2 * 16 + c]);
        }
    }

    float acc[4][4][4];
    #pragma unroll
    for (int i = 0; i < 4; i++)
        #pragma unroll
        for (int j = 0; j < 4; j++)
            #pragma unroll
            for (int q = 0; q < 4; q++) acc[i][j][q] = 0.f;

    int arow = tid >> 1, ac0 = (tid & 1) * 8;      // A tile: 128 rows x 16 cols
    int brow = tid >> 4, bc0 = (tid & 15) * 8;     // B tile: 16 rows x 128 cols
    bool avalid = (m0 + arow) < M;
    const float* Aptr = A + (size_t)(m0 + arow) * K + ac0;
    const float* Bptr = Bm + (size_t)brow * N + n0 + bc0;

    for (int k0 = 0; k0 < K; k0 += 16) {
        // ---- stage A (fp32 -> hi/lo bf16) ----
        float av[8];
        if (avalid) {
            *(float4*)(av)     = *(const float4*)(Aptr);
            *(float4*)(av + 4) = *(const float4*)(Aptr + 4);
        } else {
            #pragma unroll
            for (int q = 0; q < 8; q++) av[q] = 0.f;
        }
        Aptr += 16;
        {
            float hi[8], lo[8];
            #pragma unroll
            for (int q = 0; q < 8; q++) {
                __nv_bfloat16 h = __float2bfloat16_rn(av[q]);
                hi[q] = __bfloat162float(h);
                lo[q] = av[q] - hi[q];
            }
            uint2 uh0 = make_uint2(bfpack(hi[0], hi[1]), bfpack(hi[2], hi[3]));
            uint2 uh1 = make_uint2(bfpack(hi[4], hi[5]), bfpack(hi[6], hi[7]));
            uint2 ul0 = make_uint2(bfpack(lo[0], lo[1]), bfpack(lo[2], lo[3]));
            uint2 ul1 = make_uint2(bfpack(lo[4], lo[5]), bfpack(lo[6], lo[7]));
            *(uint2*)&Ahs[arow][ac0]     = uh0;
            *(uint2*)&Ahs[arow][ac0 + 4] = uh1;
            *(uint2*)&Als[arow][ac0]     = ul0;
            *(uint2*)&Als[arow][ac0 + 4] = ul1;
        }
        // ---- stage B ----
        {
            float bv[8];
            *(float4*)(bv)     = *(const float4*)(Bptr);
            *(float4*)(bv + 4) = *(const float4*)(Bptr + 4);
            float hi[8], lo[8];
            #pragma unroll
            for (int q = 0; q < 8; q++) {
                __nv_bfloat16 h = __float2bfloat16_rn(bv[q]);
                hi[q] = __bfloat162float(h);
                lo[q] = bv[q] - hi[q];
            }
            uint4 uh = make_uint4(bfpack(hi[0], hi[1]), bfpack(hi[2], hi[3]),
                                  bfpack(hi[4], hi[5]), bfpack(hi[6], hi[7]));
            uint4 ul = make_uint4(bfpack(lo[0], lo[1]), bfpack(lo[2], lo[3]),
                                  bfpack(lo[4], lo[5]), bfpack(lo[6], lo[7]));
            *(uint4*)&Bhs[brow][bc0] = uh;
            *(uint4*)&Bls[brow][bc0] = ul;
        }
        Bptr += (size_t)16 * N;
        __syncthreads();

        uint32_t af[4][4], bh[4][2], bl[4][2];
        #pragma unroll
        for (int i = 0; i < 4; i++) LDSM4(af[i], aAh[i]);
        #pragma unroll
        for (int j2 = 0; j2 < 2; j2++) {
            uint32_t t4[4];
            LDSM4T(t4, aBh[j2]);
            bh[2 * j2][0] = t4[0]; bh[2 * j2][1] = t4[1];
            bh[2 * j2 + 1][0] = t4[2]; bh[2 * j2 + 1][1] = t4[3];
        }
        #pragma unroll
        for (int i = 0; i < 4; i++)
            #pragma unroll
            for (int j = 0; j < 4; j++) MMA16816(acc[i][j], af[i], bh[j]);   // hi*hi
        #pragma unroll
        for (int j2 = 0; j2 < 2; j2++) {
            uint32_t t4[4];
            LDSM4T(t4, aBl[j2]);
            bl[2 * j2][0] = t4[0]; bl[2 * j2][1] = t4[1];
            bl[2 * j2 + 1][0] = t4[2]; bl[2 * j2 + 1][1] = t4[3];
        }
        #pragma unroll
        for (int i = 0; i < 4; i++)
            #pragma unroll
            for (int j = 0; j < 4; j++) MMA16816(acc[i][j], af[i], bl[j]);   // hi*lo
        #pragma unroll
        for (int i = 0; i < 4; i++) LDSM4(af[i], aAl[i]);
        #pragma unroll
        for (int i = 0; i < 4; i++)
            #pragma unroll
            for (int j = 0; j < 4; j++) MMA16816(acc[i][j], af[i], bh[j]);   // lo*hi
        __syncthreads();
    }

    // ---- epilogue ----
    #pragma unroll
    for (int i = 0; i < 4; i++) {
        int r0 = m0 + wm * 64 + i * 16 + (lane >> 2);
        #pragma unroll
        for (int h = 0; h < 2; h++) {
            int r = r0 + h * 8;
            if (r < M) {
                int ro = permute ? ((r & 31) * 128 + (r >> 5)) : r;
                #pragma unroll
                for (int j = 0; j < 4; j++) {
                    int c = n0 + wn * 32 + j * 8 + (lane & 3) * 2;
                    float x0 = acc[i][j][h * 2], x1 = acc[i][j][h * 2 + 1];
                    if (bias) { x0 += bias[c]; x1 += bias[c + 1]; }
                    *(float2*)(C + (size_t)ro * N + c) = make_float2(x0, x1);
                }
            }
        }
    }
}

// ---------------- persistent recurrence ----------------
__device__ __forceinline__ void gridsync() {
    __syncthreads();
    if (threadIdx.x == 0) {
        __threadfence();
        unsigned ticket = atomicAdd(&g_bar[0], 1u);
        unsigned phase = ticket / NCTA;
        if ((ticket % NCTA) == NCTA - 1u) {
            *(volatile unsigned*)&g_bar[1] = phase + 1u;
        } else {
            while (*(volatile unsigned*)&g_bar[1] <= phase) { }
        }
        __threadfence();
    }
    __syncthreads();
}

__device__ __forceinline__ void cell_gemm_body(const float* __restrict__ A, int lda,
                                               const float* __restrict__ W,
                                               float* __restrict__ part,
                                               int nb, int ks, float (*hs)[36]) {
    int tid = threadIdx.x;
    int kbase = ks * 64;
    __syncthreads();                             // protect hs reuse
    #pragma unroll
    for (int i = tid; i < 2048; i += 128) {
        int b = i >> 6, kk = i & 63;
        hs[kk][b] = A[b * lda + kbase + kk];
    }
    __syncthreads();
    int ncol = nb * 128 + tid;
    const float* Wp = W + (size_t)kbase * 2048 + ncol;
    ull acc[16];
    #pragma unroll
    for (int q = 0; q < 16; q++) acc[q] = 0ULL;
    for (int k0 = 0; k0 < 64; k0 += 8) {
        float wv[8];
        #pragma unroll
        for (int j = 0; j < 8; j++) wv[j] = Wp[(size_t)(k0 + j) * 2048];
        #pragma unroll
        for (int j = 0; j < 8; j++) {
            ull w2 = pack2(wv[j], wv[j]);
            const float* hr = &hs[k0 + j][0];
            #pragma unroll
            for (int p = 0; p < 8; p++) {
                ulonglong2 hh = *(const ulonglong2*)(hr + p * 4);
                ffma2(acc[2 * p], w2, hh.x);
                ffma2(acc[2 * p + 1], w2, hh.y);
            }
        }
    }
    float* pp = part + (size_t)(ks * 32) * 2048 + ncol;
    #pragma unroll
    for (int q = 0; q < 16; q++) {
        float2 v = unpack2(acc[q]);
        pp[(2 * q) * 2048] = v.x;
        pp[(2 * q + 1) * 2048] = v.y;
    }
}

__device__ __forceinline__ void combine_body(const float* __restrict__ part, int nsl,
                                             const float* __restrict__ xU,
                                             const float* __restrict__ bA,
                                             const float* __restrict__ bB,
                                             float* __restrict__ cstate,
                                             float* __restrict__ hout, int hstride,
                                             float* __restrict__ h1s) {
    int idx = blockIdx.x * 128 + threadIdx.x;    // 16384 = 32*512
    int b = idx >> 9, j = idx & 511;
    float gf = 0.f, gi = 0.f, go = 0.f, gc = 0.f;
    const float* p = part + b * 2048 + j;
    for (int s = 0; s < nsl; s++) {
        gf += p[0]; gi += p[512]; go += p[1024]; gc += p[1536];
        p += 32 * 2048;
    }
    if (xU) {
        const float* x = xU + b * 2048 + j;
        gf += x[0]; gi += x[512]; go += x[1024]; gc += x[1536];
    }
    gf += bA[j]; gi += bA[512 + j]; go += bA[1024 + j]; gc += bA[1536 + j];
    if (bB) { gf += bB[j]; gi += bB[512 + j]; go += bB[1024 + j]; gc += bB[1536 + j]; }
    float f  = 1.f / (1.f + __expf(-gf));
    float ii = 1.f / (1.f + __expf(-gi));
    float o  = 1.f / (1.f + __expf(-go));
    float cn = f * cstate[idx] + ii * tanhf(gc);
    float hn = o * tanhf(cn);
    cstate[idx] = cn;
    hout[b * hstride + j] = hn;
    if (h1s) h1s[idx] = hn;
}

__global__ __launch_bounds__(128) void recurrence_kernel(
    const float* __restrict__ Wh, const float* __restrict__ Wcat,
    const float* __restrict__ xU, const float* __restrict__ bw,
    const float* __restrict__ bu, const float* __restrict__ b1eff,
    float* __restrict__ hcat, float* __restrict__ c0s, float* __restrict__ c1s,
    float* __restrict__ part, float* __restrict__ H1s) {
    __shared__ __align__(16) float hs[64][36];
    int bid = blockIdx.x;
    for (int t = 0; t <= S_; t++) {
        // layer 0 gemm: 128 works = 16 n-blocks x 8 k-slices (K=512)
        cell_gemm_body(hcat + 512, 1024, Wh, part, bid & 15, bid >> 4, hs);
        gridsync();
        combine_body(part, 8, xU + (size_t)t * B_ * G4, bw, bu,
                     c0s, hcat + 512, 1024, nullptr);
        gridsync();
        // layer 1 gemm: 256 works = 16 n-blocks x 16 k-slices (K=1024), 2 per CTA
        cell_gemm_body(hcat, 1024, Wcat, part, bid & 15, bid >> 4, hs);
        cell_gemm_body(hcat, 1024, Wcat, part, bid & 15, (bid >> 4) + 8, hs);
        gridsync();
        combine_body(part, 16, nullptr, b1eff, nullptr,
                     c1s, hcat, 1024,
                     (t > 0) ? (H1s + (size_t)(t - 1) * B_ * H_) : nullptr);
        gridsync();
    }
}

// ---------------- host orchestration ----------------
extern "C" void kernel_launch(void* const* d_in, const int* in_sizes, int n_in,
                              void* d_out, int out_size) {
    const float* im_feat = (const float*)d_in[0];
    const int*   tokens  = (const int*)d_in[1];
    const float* h0      = (const float*)d_in[2];
    const float* c0      = (const float*)d_in[3];
    const float* embed   = (const float*)d_in[4];
    const float* W_im    = (const float*)d_in[5];
    const float* b_im    = (const float*)d_in[6];
    const float* Wh      = (const float*)d_in[7];
    const float* bw      = (const float*)d_in[8];
    const float* Uh      = (const float*)d_in[9];
    const float* bu      = (const float*)d_in[10];
    const float* Wxh     = (const float*)d_in[11];
    const float* bxh     = (const float*)d_in[12];
    const float* Wc      = (const float*)d_in[13];
    const float* bc      = (const float*)d_in[14];
    float* out = (float*)d_out;

    float *yim, *Xg, *xU, *Wcat, *b1eff, *hcat, *c0s, *c1s, *part, *H1s, *ys;
    cudaGetSymbolAddress((void**)&yim,   g_yim);
    cudaGetSymbolAddress((void**)&Xg,    g_Xg);
    cudaGetSymbolAddress((void**)&xU,    g_xU);
    cudaGetSymbolAddress((void**)&Wcat,  g_Wcat);
    cudaGetSymbolAddress((void**)&b1eff, g_b1eff);
    cudaGetSymbolAddress((void**)&hcat,  g_hcat);
    cudaGetSymbolAddress((void**)&c0s,   g_c0s);
    cudaGetSymbolAddress((void**)&c1s,   g_c1s);
    cudaGetSymbolAddress((void**)&part,  g_part);
    cudaGetSymbolAddress((void**)&H1s,   g_H1s);
    cudaGetSymbolAddress((void**)&ys,    g_ys);

    // states + barrier reset
    init_state_kernel<<<128, 256>>>(h0, c0, hcat, c0s, c1s);
    // y_im = im_feat @ W_im + b_im        [32,768]@[768,512] (fp32, tiny)
    sgemm_kernel<<<dim3(D_ / 128, 1), 256>>>(im_feat, W_im, b_im, yim, B_, D_, F_, 0);
    // gather step inputs
    gather_kernel<<<((S_ + 1) * B_ * D_ / 4) / 256, 256>>>(yim, embed, tokens, Xg);
    // xU = Xg @ Uh0                        [4128,512]@[512,2048] (tensor cores)
    bf3_gemm_kernel<<<dim3(G4 / 128, ((S_ + 1) * B_ + 127) / 128), 256>>>(
        Xg, Uh, nullptr, xU, (S_ + 1) * B_, G4, D_, 0);
    // Wcat = [Wh1 ; Wxh0 @ Uh1]  (fp32 for recurrence-weight precision)
    cudaMemcpyAsync(Wcat, Wh + (size_t)H_ * G4, sizeof(float) * H_ * G4,
                    cudaMemcpyDeviceToDevice, 0);
    sgemm_kernel<<<dim3(G4 / 128, H_ / 128), 256>>>(
        Wxh, Uh + (size_t)D_ * G4, nullptr, Wcat + (size_t)H_ * G4, H_, G4, H_, 0);
    b1eff_kernel<<<G4 / 256, 256>>>(bw, bu, bxh, Uh, b1eff);

    // full recurrence: one persistent kernel, 129 steps
    recurrence_kernel<<<NCTA, 128>>>(Wh, Wcat, xU, bw, bu, b1eff,
                                     hcat, c0s, c1s, part, H1s);

    // ys = H1s @ Wxh1 + bxh1               [4096,512]@[512,512]
    bf3_gemm_kernel<<<dim3(D_ / 128, S_ * B_ / 128), 256>>>(
        H1s, Wxh + (size_t)H_ * D_, bxh + D_, ys, S_ * B_, D_, H_, 0);
    // logits = ys @ Wc + bc                [4096,512]@[512,32000], permuted rows
    bf3_gemm_kernel<<<dim3(V_ / 128, S_ * B_ / 128), 256>>>(
        ys, Wc, bc, out, S_ * B_, V_, D_, 1);
}

// round 5
// speedup vs baseline: 1.4238x; 1.4238x over previous
#include <cuda_runtime.h>
#include <cuda_bf16.h>
#include <cstdint>

typedef unsigned long long ull;

#define B_  32
#define S_  128
#define H_  512
#define D_  512
#define V_  32000
#define F_  768
#define G4  2048   // 4*H

// ---------------- scratch (device globals; no allocation allowed) ----------------
__device__ float g_yim[B_ * D_];
__device__ float g_Xg[(S_ + 1) * B_ * D_];
__device__ float g_xU[(S_ + 1) * B_ * G4];
__device__ float g_Wcat[1024 * G4];              // [Wh1 ; M01=Wxh0@Uh1]
__device__ float g_b1eff[G4];
__device__ float g_hcat[B_ * 1024];              // per row: [h1 | h0']
__device__ float g_c0a[B_ * H_];
__device__ float g_c0b[B_ * H_];
__device__ float g_c1s[B_ * H_];
__device__ float g_part0[8 * B_ * G4];
__device__ float g_part1[16 * B_ * G4];
__device__ float g_H1s[S_ * B_ * H_];
__device__ float g_ys[S_ * B_ * D_];

// pre-split bf16 hi/lo operand arrays
__device__ __nv_bfloat16 g_Uh_h[512 * 2048], g_Uh_l[512 * 2048];
__device__ __nv_bfloat16 g_Wx1_h[512 * 512], g_Wx1_l[512 * 512];
__device__ __nv_bfloat16 g_Wc_h[512 * 32000], g_Wc_l[512 * 32000];
__device__ __nv_bfloat16 g_Xg_h[4224 * 512], g_Xg_l[4224 * 512];   // padded to 33*128 rows
__device__ __nv_bfloat16 g_H1s_h[4096 * 512], g_H1s_l[4096 * 512];
__device__ __nv_bfloat16 g_ys_h[4096 * 512], g_ys_l[4096 * 512];

// ---------------- packed fp32x2 helpers ----------------
__device__ __forceinline__ ull pack2(float x, float y) {
    ull r; asm("mov.b64 %0, {%1, %2};" : "=l"(r) : "f"(x), "f"(y)); return r;
}
__device__ __forceinline__ void ffma2(ull& d, ull a, ull b) {
    asm("fma.rn.f32x2 %0, %1, %2, %0;" : "+l"(d) : "l"(a), "l"(b));
}
__device__ __forceinline__ float2 unpack2(ull v) {
    float2 r; asm("mov.b64 {%0, %1}, %2;" : "=f"(r.x), "=f"(r.y) : "l"(v)); return r;
}
__device__ __forceinline__ uint32_t smem_u32(const void* p) {
    return (uint32_t)__cvta_generic_to_shared(p);
}

// ---------------- init ----------------
__global__ void init_state_kernel(const float* __restrict__ h0,
                                  const float* __restrict__ c0,
                                  float* __restrict__ hcat,
                                  float* __restrict__ c0a,
                                  float* __restrict__ c1s) {
    int idx = blockIdx.x * 256 + threadIdx.x;   // 32768
    int l = idx >> 14, b = (idx >> 9) & 31, j = idx & 511;
    float h = h0[idx], c = c0[idx];
    if (l == 0) { hcat[b * 1024 + 512 + j] = h; c0a[b * 512 + j] = c; }
    else        { hcat[b * 1024 + j] = h;       c1s[b * 512 + j] = c; }
}

// ---------------- gather ----------------
__global__ void gather_kernel(const float* __restrict__ yim,
                              const float* __restrict__ embed,
                              const int* __restrict__ tokens,
                              float* __restrict__ Xg) {
    int v = blockIdx.x * 256 + threadIdx.x;
    int d4 = v & 127;
    int bt = v >> 7;
    int b = bt & 31;
    int t = bt >> 5;
    const float4* src;
    if (t == 0) src = (const float4*)(yim + b * 512);
    else        src = (const float4*)(embed + (size_t)tokens[b * 128 + (t - 1)] * 512);
    ((float4*)Xg)[v] = src[d4];
}

// ---------------- b1eff ----------------
__global__ void b1eff_kernel(const float* __restrict__ bw, const float* __restrict__ bu,
                             const float* __restrict__ bxh, const float* __restrict__ Uh,
                             float* __restrict__ b1) {
    int n = blockIdx.x * 256 + threadIdx.x;
    float acc = bw[2048 + n] + bu[2048 + n];
    const float* U1 = Uh + 512 * 2048;
    for (int k = 0; k < 512; k++) acc += bxh[k] * U1[k * 2048 + n];
    b1[n] = acc;
}

// ---------------- fp32 -> bf16 hi/lo split ----------------
__global__ void split_kernel(const float* __restrict__ in,
                             __nv_bfloat16* __restrict__ hi,
                             __nv_bfloat16* __restrict__ lo, int n8) {
    int i = blockIdx.x * 256 + threadIdx.x;
    if (i >= n8) return;
    float4 a = ((const float4*)in)[2 * i];
    float4 b = ((const float4*)in)[2 * i + 1];
    float v[8] = {a.x, a.y, a.z, a.w, b.x, b.y, b.z, b.w};
    unsigned h[8], l[8];
    #pragma unroll
    for (int q = 0; q < 8; q++) {
        __nv_bfloat16 hh = __float2bfloat16_rn(v[q]);
        h[q] = (unsigned)__bfloat16_as_ushort(hh);
        float lof = v[q] - __bfloat162float(hh);
        l[q] = (unsigned)__bfloat16_as_ushort(__float2bfloat16_rn(lof));
    }
    uint4 uh = make_uint4(h[0] | (h[1] << 16), h[2] | (h[3] << 16),
                          h[4] | (h[5] << 16), h[6] | (h[7] << 16));
    uint4 ul = make_uint4(l[0] | (l[1] << 16), l[2] | (l[3] << 16),
                          l[4] | (l[5] << 16), l[6] | (l[7] << 16));
    ((uint4*)hi)[i] = uh;
    ((uint4*)lo)[i] = ul;
}

// ---------------- fp32 SGEMM (small setup matrices) ----------------
__global__ __launch_bounds__(256, 2) void sgemm_kernel(const float* __restrict__ A,
                                                       const float* __restrict__ Bm,
                                                       const float* __restrict__ bias,
                                                       float* __restrict__ C,
                                                       int M, int N, int K, int permute) {
    __shared__ __align__(16) float As[16][132];
    __shared__ __align__(16) float Bs[16][128];
    int tid = threadIdx.x;
    int m0 = blockIdx.y * 128, n0 = blockIdx.x * 128;
    int a_m = tid >> 2, a_k = (tid & 3) << 2;
    int b_k = tid >> 5, b_n = (tid & 31) << 2;
    int tm0 = (tid >> 4) << 3, tn0 = (tid & 15) << 3;
    ull acc[8][4];
    #pragma unroll
    for (int i = 0; i < 8; i++)
        #pragma unroll
        for (int j = 0; j < 4; j++) acc[i][j] = 0ULL;

    for (int k0 = 0; k0 < K; k0 += 16) {
        #pragma unroll
        for (int h = 0; h < 2; h++) {
            int gm = m0 + a_m + h * 64;
            float4 av = make_float4(0.f, 0.f, 0.f, 0.f);
            if (gm < M) av = *(const float4*)(A + (size_t)gm * K + k0 + a_k);
            As[a_k + 0][a_m + h * 64] = av.x;
            As[a_k + 1][a_m + h * 64] = av.y;
            As[a_k + 2][a_m + h * 64] = av.z;
            As[a_k + 3][a_m + h * 64] = av.w;
        }
        #pragma unroll
        for (int h = 0; h < 2; h++) {
            int gk = k0 + b_k + h * 8;
            *(float4*)&Bs[b_k + h * 8][b_n] = *(const float4*)(Bm + (size_t)gk * N + n0 + b_n);
        }
        __syncthreads();
        #pragma unroll
        for (int kk = 0; kk < 16; kk++) {
            float4 a0 = *(const float4*)&As[kk][tm0];
            float4 a1 = *(const float4*)&As[kk][tm0 + 4];
            ull b2[4];
            #pragma unroll
            for (int j = 0; j < 4; j++) b2[j] = *(const ull*)&Bs[kk][tn0 + 2 * j];
            float av[8] = {a0.x, a0.y, a0.z, a0.w, a1.x, a1.y, a1.z, a1.w};
            #pragma unroll
            for (int i = 0; i < 8; i++) {
                ull a2 = pack2(av[i], av[i]);
                #pragma unroll
                for (int j = 0; j < 4; j++) ffma2(acc[i][j], a2, b2[j]);
            }
        }
        __syncthreads();
    }
    #pragma unroll
    for (int i = 0; i < 8; i++) {
        int r = m0 + tm0 + i;
        if (r < M) {
            int ro = permute ? ((r & 31) * 128 + (r >> 5)) : r;
            float o_[8];
            #pragma unroll
            for (int j = 0; j < 4; j++) {
                float2 v = unpack2(acc[i][j]);
                o_[2 * j] = v.x; o_[2 * j + 1] = v.y;
            }
            if (bias) {
                #pragma unroll
                for (int j = 0; j < 8; j++) o_[j] += bias[n0 + tn0 + j];
            }
            float* cp = C + (size_t)ro * N + n0 + tn0;
            *(float4*)cp = make_float4(o_[0], o_[1], o_[2], o_[3]);
            *(float4*)(cp + 4) = make_float4(o_[4], o_[5], o_[6], o_[7]);
        }
    }
}

// ---------------- bf16-pair tensor-core GEMM (pre-split operands) ----------------
// C = Ah@Bh + Ah@Bl + Al@Bh (+bias). A arrays must be row-padded to 128 multiples.
#define LDSM4(r, addr) asm volatile( \
    "ldmatrix.sync.aligned.m8n8.x4.shared.b16 {%0,%1,%2,%3}, [%4];" \
    : "=r"((r)[0]), "=r"((r)[1]), "=r"((r)[2]), "=r"((r)[3]) : "r"(addr))
#define LDSM4T(r, addr) asm volatile( \
    "ldmatrix.sync.aligned.m8n8.x4.trans.shared.b16 {%0,%1,%2,%3}, [%4];" \
    : "=r"((r)[0]), "=r"((r)[1]), "=r"((r)[2]), "=r"((r)[3]) : "r"(addr))
#define MMA16816(d, a, b) asm volatile( \
    "mma.sync.aligned.m16n8k16.row.col.f32.bf16.bf16.f32 " \
    "{%0,%1,%2,%3}, {%4,%5,%6,%7}, {%8,%9}, {%0,%1,%2,%3};" \
    : "+f"((d)[0]), "+f"((d)[1]), "+f"((d)[2]), "+f"((d)[3]) \
    : "r"((a)[0]), "r"((a)[1]), "r"((a)[2]), "r"((a)[3]), "r"((b)[0]), "r"((b)[1]))

__global__ __launch_bounds__(256) void bfp_gemm_kernel(
    const __nv_bfloat16* __restrict__ Ah, const __nv_bfloat16* __restrict__ Al,
    const __nv_bfloat16* __restrict__ Bh, const __nv_bfloat16* __restrict__ Bl,
    const float* __restrict__ bias, float* __restrict__ C,
    int M, int N, int K, int permute) {
    __shared__ __align__(16) __nv_bfloat16 Ahs[128][24];
    __shared__ __align__(16) __nv_bfloat16 Als[128][24];
    __shared__ __align__(16) __nv_bfloat16 Bhs[16][136];
    __shared__ __align__(16) __nv_bfloat16 Bls[16][136];
    int tid = threadIdx.x;
    int lane = tid & 31, wid = tid >> 5;
    int wm = wid >> 2, wn = wid & 3;           // 2 x 4 warps, warp tile 64m x 32n
    int m0 = blockIdx.y * 128, n0 = blockIdx.x * 128;

    uint32_t aAh[4], aAl[4], aBh[2], aBl[2];
    {
        int r = lane & 15, c = (lane >> 4) * 8;
        #pragma unroll
        for (int i = 0; i < 4; i++) {
            aAh[i] = smem_u32(&Ahs[wm * 64 + i * 16 + r][c]);
            aAl[i] = smem_u32(&Als[wm * 64 + i * 16 + r][c]);
        }
        #pragma unroll
        for (int j2 = 0; j2 < 2; j2++) {
            aBh[j2] = smem_u32(&Bhs[r][wn * 32 + j2 * 16 + c]);
            aBl[j2] = smem_u32(&Bls[r][wn * 32 + j2 * 16 + c]);
        }
    }

    float acc[4][4][4];
    #pragma unroll
    for (int i = 0; i < 4; i++)
        #pragma unroll
        for (int j = 0; j < 4; j++)
            #pragma unroll
            for (int q = 0; q < 4; q++) acc[i][j][q] = 0.f;

    int arow = tid >> 1, ac0 = (tid & 1) * 8;      // A tile 128x16
    int brow = tid >> 4, bc0 = (tid & 15) * 8;     // B tile 16x128
    const __nv_bfloat16* Ahp = Ah + (size_t)(m0 + arow) * K + ac0;
    const __nv_bfloat16* Alp = Al + (size_t)(m0 + arow) * K + ac0;
    const __nv_bfloat16* Bhp = Bh + (size_t)brow * N + n0 + bc0;
    const __nv_bfloat16* Blp = Bl + (size_t)brow * N + n0 + bc0;
    uint4 rAh = *(const uint4*)Ahp, rAl = *(const uint4*)Alp;
    uint4 rBh = *(const uint4*)Bhp, rBl = *(const uint4*)Blp;

    for (int k0 = 0; k0 < K; k0 += 16) {
        *(uint4*)&Ahs[arow][ac0] = rAh;
        *(uint4*)&Als[arow][ac0] = rAl;
        *(uint4*)&Bhs[brow][bc0] = rBh;
        *(uint4*)&Bls[brow][bc0] = rBl;
        __syncthreads();
        if (k0 + 16 < K) {   // software-pipelined prefetch of next tile
            Ahp += 16; Alp += 16;
            Bhp += (size_t)16 * N; Blp += (size_t)16 * N;
            rAh = *(const uint4*)Ahp; rAl = *(const uint4*)Alp;
            rBh = *(const uint4*)Bhp; rBl = *(const uint4*)Blp;
        }
        uint32_t af[4][4], bh[4][2], bl[4][2];
        #pragma unroll
        for (int i = 0; i < 4; i++) LDSM4(af[i], aAh[i]);
        #pragma unroll
        for (int j2 = 0; j2 < 2; j2++) {
            uint32_t t4[4];
            LDSM4T(t4, aBh[j2]);
            bh[2 * j2][0] = t4[0]; bh[2 * j2][1] = t4[1];
            bh[2 * j2 + 1][0] = t4[2]; bh[2 * j2 + 1][1] = t4[3];
        }
        #pragma unroll
        for (int i = 0; i < 4; i++)
            #pragma unroll
            for (int j = 0; j < 4; j++) MMA16816(acc[i][j], af[i], bh[j]);   // hi*hi
        #pragma unroll
        for (int j2 = 0; j2 < 2; j2++) {
            uint32_t t4[4];
            LDSM4T(t4, aBl[j2]);
            bl[2 * j2][0] = t4[0]; bl[2 * j2][1] = t4[1];
            bl[2 * j2 + 1][0] = t4[2]; bl[2 * j2 + 1][1] = t4[3];
        }
        #pragma unroll
        for (int i = 0; i < 4; i++)
            #pragma unroll
            for (int j = 0; j < 4; j++) MMA16816(acc[i][j], af[i], bl[j]);   // hi*lo
        #pragma unroll
        for (int i = 0; i < 4; i++) LDSM4(af[i], aAl[i]);
        #pragma unroll
        for (int i = 0; i < 4; i++)
            #pragma unroll
            for (int j = 0; j < 4; j++) MMA16816(acc[i][j], af[i], bh[j]);   // lo*hi
        __syncthreads();
    }

    #pragma unroll
    for (int i = 0; i < 4; i++) {
        int r0 = m0 + wm * 64 + i * 16 + (lane >> 2);
        #pragma unroll
        for (int h = 0; h < 2; h++) {
            int r = r0 + h * 8;
            if (r < M) {
                int ro = permute ? ((r & 31) * 128 + (r >> 5)) : r;
                #pragma unroll
                for (int j = 0; j < 4; j++) {
                    int c = n0 + wn * 32 + j * 8 + (lane & 3) * 2;
                    float x0 = acc[i][j][h * 2], x1 = acc[i][j][h * 2 + 1];
                    if (bias) { x0 += bias[c]; x1 += bias[c + 1]; }
                    *(float2*)(C + (size_t)ro * N + c) = make_float2(x0, x1);
                }
            }
        }
    }
}

// ---------------- LSTM cell pieces ----------------
__device__ __forceinline__ float4 gates0_fn(int b, int j,
                                            const float* __restrict__ part0,
                                            const float* __restrict__ xU_t,
                                            const float* __restrict__ bw,
                                            const float* __restrict__ bu) {
    float gf = 0.f, gi = 0.f, go = 0.f, gc = 0.f;
    const float* p = part0 + b * 2048 + j;
    #pragma unroll
    for (int s = 0; s < 8; s++) {
        gf += p[0]; gi += p[512]; go += p[1024]; gc += p[1536];
        p += 32 * 2048;
    }
    const float* x = xU_t + b * 2048 + j;
    gf += x[0]    + bw[j]        + bu[j];
    gi += x[512]  + bw[512 + j]  + bu[512 + j];
    go += x[1024] + bw[1024 + j] + bu[1024 + j];
    gc += x[1536] + bw[1536 + j] + bu[1536 + j];
    return make_float4(gf, gi, go, gc);
}

__device__ __forceinline__ float2 lstm_update(float4 g, float c_old) {
    float f  = 1.f / (1.f + __expf(-g.x));
    float ii = 1.f / (1.f + __expf(-g.y));
    float o  = 1.f / (1.f + __expf(-g.z));
    float cn = f * c_old + ii * tanhf(g.w);
    float hn = o * tanhf(cn);
    return make_float2(hn, cn);
}

// shared 64-k-slice GEMM body: part_out[r*2048 + ncol] over 32 batch rows
__device__ __forceinline__ void gemm64(const float* __restrict__ Wp,   // + kbase*2048 + ncol
                                       float* __restrict__ pout,       // + ks*32*2048 + ncol
                                       float (*hs)[36]) {
    ull acc[16];
    #pragma unroll
    for (int q = 0; q < 16; q++) acc[q] = 0ULL;
    for (int k0 = 0; k0 < 64; k0 += 8) {
        float wv[8];
        #pragma unroll
        for (int j = 0; j < 8; j++) wv[j] = Wp[(size_t)(k0 + j) * 2048];
        #pragma unroll
        for (int j = 0; j < 8; j++) {
            ull w2 = pack2(wv[j], wv[j]);
            const float* hr = &hs[k0 + j][0];
            #pragma unroll
            for (int p = 0; p < 8; p++) {
                ulonglong2 hh = *(const ulonglong2*)(hr + p * 4);
                ffma2(acc[2 * p], w2, hh.x);
                ffma2(acc[2 * p + 1], w2, hh.y);
            }
        }
    }
    #pragma unroll
    for (int q = 0; q < 16; q++) {
        float2 v = unpack2(acc[q]);
        pout[(2 * q) * 2048] = v.x;
        pout[(2 * q + 1) * 2048] = v.y;
    }
}

// bootstrap layer-0 GEMM (t=0): A = hcat+512
__global__ __launch_bounds__(128) void cell_gemm_kernel(const float* __restrict__ A, int lda,
                                                        const float* __restrict__ W,
                                                        float* __restrict__ part) {
    __shared__ __align__(16) float hs[64][36];
    int tid = threadIdx.x;
    int kbase = blockIdx.y * 64;
    for (int i = tid; i < 2048; i += 128) {
        int b = i >> 6, kk = i & 63;
        hs[kk][b] = A[b * lda + kbase + kk];
    }
    __syncthreads();
    int ncol = blockIdx.x * 128 + tid;
    gemm64(W + (size_t)kbase * 2048 + ncol,
           part + (size_t)(blockIdx.y * 32) * 2048 + ncol, hs);
}

// step A: fused combine0 + layer-1 GEMM.  grid (16 nb, 16 ks), 128 threads.
__global__ __launch_bounds__(128) void stepA_kernel(
    const float* __restrict__ Wcat, const float* __restrict__ part0,
    float* __restrict__ part1, const float* __restrict__ xU_t,
    const float* __restrict__ bw, const float* __restrict__ bu,
    const float* __restrict__ c0_old, float* __restrict__ c0_new,
    float* __restrict__ hcat) {
    __shared__ __align__(16) float hs[64][36];
    int tid = threadIdx.x, nb = blockIdx.x, ks = blockIdx.y;

    if (ks < 8) {
        // distributed combine0 share (128 CTAs x 128 thr = 16384 values)
        int idx = (ks * 16 + nb) * 128 + tid;
        int b = idx >> 9, j = idx & 511;
        float4 g = gates0_fn(b, j, part0, xU_t, bw, bu);
        float2 hc = lstm_update(g, c0_old[idx]);
        c0_new[idx] = hc.y;
        hcat[b * 1024 + 512 + j] = hc.x;            // h0' for next kernel
        // smem tile from h1 (written last step, kernel boundary)
        for (int i = tid; i < 2048; i += 128) {
            int bb = i >> 6, kk = i & 63;
            hs[kk][bb] = hcat[bb * 1024 + ks * 64 + kk];
        }
    } else {
        // recompute this slice's h0' columns directly into smem (same math as share)
        for (int i = tid; i < 2048; i += 128) {
            int bb = i >> 6, kk = i & 63;
            int j = (ks - 8) * 64 + kk;
            float4 g = gates0_fn(bb, j, part0, xU_t, bw, bu);
            float2 hc = lstm_update(g, c0_old[bb * 512 + j]);
            hs[kk][bb] = hc.x;
        }
    }
    __syncthreads();
    int ncol = nb * 128 + tid;
    gemm64(Wcat + (size_t)(ks * 64) * 2048 + ncol,
           part1 + (size_t)(ks * 32) * 2048 + ncol, hs);
}

// step B: fused combine1 + next step's layer-0 GEMM.  grid (16 nb, 8 ks), 128 threads.
__global__ __launch_bounds__(128) void stepB_kernel(
    const float* __restrict__ Wh, const float* __restrict__ part1,
    float* __restrict__ part0, const float* __restrict__ b1eff,
    float* __restrict__ c1s, float* __restrict__ hcat,
    float* __restrict__ H1s_t) {
    __shared__ __align__(16) float hs[64][36];
    int tid = threadIdx.x, nb = blockIdx.x, ks = blockIdx.y;
    {
        int idx = (ks * 16 + nb) * 128 + tid;       // 16384 total
        int b = idx >> 9, j = idx & 511;
        float gf = 0.f, gi = 0.f, go = 0.f, gc = 0.f;
        const float* p = part1 + b * 2048 + j;
        #pragma unroll
        for (int s = 0; s < 16; s++) {
            gf += p[0]; gi += p[512]; go += p[1024]; gc += p[1536];
            p += 32 * 2048;
        }
        gf += b1eff[j]; gi += b1eff[512 + j]; go += b1eff[1024 + j]; gc += b1eff[1536 + j];
        float2 hc = lstm_update(make_float4(gf, gi, go, gc), c1s[idx]);
        c1s[idx] = hc.y;                            // in-place safe: sole reader/writer
        hcat[b * 1024 + j] = hc.x;                  // h1 (read by next stepA, disjoint here)
        if (H1s_t) H1s_t[idx] = hc.x;
    }
    // layer-0 GEMM reads only h0' (hcat+512, written by stepA) — independent of combine1
    for (int i = tid; i < 2048; i += 128) {
        int bb = i >> 6, kk = i & 63;
        hs[kk][bb] = hcat[bb * 1024 + 512 + ks * 64 + kk];
    }
    __syncthreads();
    int ncol = nb * 128 + tid;
    gemm64(Wh + (size_t)(ks * 64) * 2048 + ncol,
           part0 + (size_t)(ks * 32) * 2048 + ncol, hs);
}

// final standalone combine (t = S)
__global__ void cell_combine_kernel(const float* __restrict__ part,
                                    const float* __restrict__ b1eff,
                                    float* __restrict__ c1s,
                                    float* __restrict__ h1s) {
    int idx = blockIdx.x * 256 + threadIdx.x;   // 16384
    int b = idx >> 9, j = idx & 511;
    float gf = 0.f, gi = 0.f, go = 0.f, gc = 0.f;
    const float* p = part + b * 2048 + j;
    #pragma unroll
    for (int s = 0; s < 16; s++) {
        gf += p[0]; gi += p[512]; go += p[1024]; gc += p[1536];
        p += 32 * 2048;
    }
    gf += b1eff[j]; gi += b1eff[512 + j]; go += b1eff[1024 + j]; gc += b1eff[1536 + j];
    float2 hc = lstm_update(make_float4(gf, gi, go, gc), c1s[idx]);
    c1s[idx] = hc.y;
    h1s[idx] = hc.x;
}

// ---------------- host orchestration ----------------
extern "C" void kernel_launch(void* const* d_in, const int* in_sizes, int n_in,
                              void* d_out, int out_size) {
    const float* im_feat = (const float*)d_in[0];
    const int*   tokens  = (const int*)d_in[1];
    const float* h0      = (const float*)d_in[2];
    const float* c0      = (const float*)d_in[3];
    const float* embed   = (const float*)d_in[4];
    const float* W_im    = (const float*)d_in[5];
    const float* b_im    = (const float*)d_in[6];
    const float* Wh      = (const float*)d_in[7];
    const float* bw      = (const float*)d_in[8];
    const float* Uh      = (const float*)d_in[9];
    const float* bu      = (const float*)d_in[10];
    const float* Wxh     = (const float*)d_in[11];
    const float* bxh     = (const float*)d_in[12];
    const float* Wc      = (const float*)d_in[13];
    const float* bc      = (const float*)d_in[14];
    float* out = (float*)d_out;

    float *yim, *Xg, *xU, *Wcat, *b1eff, *hcat, *c0a, *c0b, *c1s, *part0, *part1, *H1s, *ys;
    __nv_bfloat16 *Uh_h, *Uh_l, *Wx1_h, *Wx1_l, *Wc_h, *Wc_l, *Xg_h, *Xg_l, *H1_h, *H1_l, *ys_h, *ys_l;
    cudaGetSymbolAddress((void**)&yim,   g_yim);
    cudaGetSymbolAddress((void**)&Xg,    g_Xg);
    cudaGetSymbolAddress((void**)&xU,    g_xU);
    cudaGetSymbolAddress((void**)&Wcat,  g_Wcat);
    cudaGetSymbolAddress((void**)&b1eff, g_b1eff);
    cudaGetSymbolAddress((void**)&hcat,  g_hcat);
    cudaGetSymbolAddress((void**)&c0a,   g_c0a);
    cudaGetSymbolAddress((void**)&c0b,   g_c0b);
    cudaGetSymbolAddress((void**)&c1s,   g_c1s);
    cudaGetSymbolAddress((void**)&part0, g_part0);
    cudaGetSymbolAddress((void**)&part1, g_part1);
    cudaGetSymbolAddress((void**)&H1s,   g_H1s);
    cudaGetSymbolAddress((void**)&ys,    g_ys);
    cudaGetSymbolAddress((void**)&Uh_h,  g_Uh_h);
    cudaGetSymbolAddress((void**)&Uh_l,  g_Uh_l);
    cudaGetSymbolAddress((void**)&Wx1_h, g_Wx1_h);
    cudaGetSymbolAddress((void**)&Wx1_l, g_Wx1_l);
    cudaGetSymbolAddress((void**)&Wc_h,  g_Wc_h);
    cudaGetSymbolAddress((void**)&Wc_l,  g_Wc_l);
    cudaGetSymbolAddress((void**)&Xg_h,  g_Xg_h);
    cudaGetSymbolAddress((void**)&Xg_l,  g_Xg_l);
    cudaGetSymbolAddress((void**)&H1_h,  g_H1s_h);
    cudaGetSymbolAddress((void**)&H1_l,  g_H1s_l);
    cudaGetSymbolAddress((void**)&ys_h,  g_ys_h);
    cudaGetSymbolAddress((void**)&ys_l,  g_ys_l);

    // ---- setup ----
    init_state_kernel<<<128, 256>>>(h0, c0, hcat, c0a, c1s);
    sgemm_kernel<<<dim3(D_ / 128, 1), 256>>>(im_feat, W_im, b_im, yim, B_, D_, F_, 0);
    gather_kernel<<<((S_ + 1) * B_ * D_ / 4) / 256, 256>>>(yim, embed, tokens, Xg);

    // weight splits (can run early; independent)
    split_kernel<<<(512 * 2048 / 8 + 255) / 256, 256>>>(Uh, Uh_h, Uh_l, 512 * 2048 / 8);
    split_kernel<<<(512 * 512 / 8 + 255) / 256, 256>>>(Wxh + (size_t)H_ * D_, Wx1_h, Wx1_l, 512 * 512 / 8);
    split_kernel<<<(512 * 32000 / 8 + 255) / 256, 256>>>(Wc, Wc_h, Wc_l, 512 * 32000 / 8);
    split_kernel<<<((S_ + 1) * B_ * D_ / 8 + 255) / 256, 256>>>(Xg, Xg_h, Xg_l, (S_ + 1) * B_ * D_ / 8);

    // xU = Xg @ Uh0   [4128,512]@[512,2048]  (bf16-pair TC)
    bfp_gemm_kernel<<<dim3(G4 / 128, 33), 256>>>(Xg_h, Xg_l, Uh_h, Uh_l,
                                                 nullptr, xU, (S_ + 1) * B_, G4, D_, 0);
    // Wcat = [Wh1 ; Wxh0 @ Uh1]  (fp32 — recurrence weights stay full precision)
    cudaMemcpyAsync(Wcat, Wh + (size_t)H_ * G4, sizeof(float) * H_ * G4,
                    cudaMemcpyDeviceToDevice, 0);
    sgemm_kernel<<<dim3(G4 / 128, H_ / 128), 256>>>(
        Wxh, Uh + (size_t)D_ * G4, nullptr, Wcat + (size_t)H_ * G4, H_, G4, H_, 0);
    b1eff_kernel<<<G4 / 256, 256>>>(bw, bu, bxh, Uh, b1eff);

    // ---- recurrence: bootstrap + 2 kernels per step ----
    cell_gemm_kernel<<<dim3(16, 8), 128>>>(hcat + 512, 1024, Wh, part0);
    for (int t = 0; t <= S_; t++) {
        const float* c0r = (t & 1) ? c0b : c0a;
        float* c0w       = (t & 1) ? c0a : c0b;
        stepA_kernel<<<dim3(16, 16), 128>>>(Wcat, part0, part1, xU + (size_t)t * B_ * G4,
                                            bw, bu, c0r, c0w, hcat);
        if (t < S_) {
            stepB_kernel<<<dim3(16, 8), 128>>>(Wh, part1, part0, b1eff, c1s, hcat,
                                               (t > 0) ? (H1s + (size_t)(t - 1) * B_ * H_)
                                                       : nullptr);
        } else {
            cell_combine_kernel<<<64, 256>>>(part1, b1eff, c1s,
                                             H1s + (size_t)(S_ - 1) * B_ * H_);
        }
    }

    // ---- output path ----
    split_kernel<<<(S_ * B_ * H_ / 8 + 255) / 256, 256>>>(H1s, H1_h, H1_l, S_ * B_ * H_ / 8);
    // ys = H1s @ Wxh1 + bxh1   [4096,512]@[512,512]
    bfp_gemm_kernel<<<dim3(D_ / 128, S_ * B_ / 128), 256>>>(
        H1_h, H1_l, Wx1_h, Wx1_l, bxh + D_, ys, S_ * B_, D_, H_, 0);
    split_kernel<<<(S_ * B_ * D_ / 8 + 255) / 256, 256>>>(ys, ys_h, ys_l, S_ * B_ * D_ / 8);
    // logits = ys @ Wc + bc    [4096,512]@[512,32000], rows (t,b)->(b,t)
    bfp_gemm_kernel<<<dim3(V_ / 128, S_ * B_ / 128), 256>>>(
        ys_h, ys_l, Wc_h, Wc_l, bc, out, S_ * B_, V_, D_, 1);
}